// round 4
// baseline (speedup 1.0000x reference)
#include <cuda_runtime.h>
#include <cstdint>

// Problem constants
#define SDIM   64
#define CIN    16
#define COUTC  16
#define BATCH  4

// Tiling
#define TY         4
#define TXT        8
#define XPT        8
#define CPT        4
#define NTHREADS 128

// Windowed input tile: 8 windows of 10 floats per row (conflict-free LDS.64),
// rows: z:3 * y:6 = 18, row width 80 floats.
#define WIN_W      10
#define NWIN       8
#define IN_ROW     (NWIN * WIN_W)     // 80
#define IN_H       (TY + 2)           // 6
#define IN_D       3
#define TILE_ELEMS (IN_D * IN_H * IN_ROW)   // 1440
#define SLOTS_PER_THREAD ((TILE_ELEMS + NTHREADS - 1) / NTHREADS)  // 12

// Shared weights, transposed: [(cin*3+kd)*3+kh][kw*16 + cout]
#define W_ELEMS (CIN * 9 * 48)

#define PACKF2(d, lo, hi) \
    asm("mov.b64 %0, {%1, %2};" : "=l"(d) : "f"(lo), "f"(hi))
#define FMAF2(d, a, b, c) \
    asm("fma.rn.f32x2 %0, %1, %2, %3;" : "=l"(d) : "l"(a), "l"(b), "l"(c))
#define UNPACKF2(lo, hi, s) \
    asm("mov.b64 {%0, %1}, %2;" : "=f"(lo), "=f"(hi) : "l"(s))

__device__ __forceinline__ uint32_t smem_u32(const void* p) {
    return (uint32_t)__cvta_generic_to_shared(p);
}

__global__ void __launch_bounds__(NTHREADS)
conv3d_kernel(const float* __restrict__ X,
              const float* __restrict__ Wg,
              const float* __restrict__ Bias,
              float* __restrict__ Out)
{
    __shared__ __align__(16) float s_w[W_ELEMS];
    __shared__ float s_bias[COUTC];
    __shared__ __align__(16) float s_in[2][TILE_ELEMS];

    const int tid = threadIdx.x;
    const int tx  = tid & (TXT - 1);
    const int ty  = (tid >> 3) & (TY - 1);
    const int cg  = tid >> 5;

    const int z  = blockIdx.x;
    const int y0 = blockIdx.y * TY;
    const int b  = blockIdx.z;

    // ---- Weights: load + transpose into shared ----
    for (int g = tid; g < COUTC * CIN * 27; g += NTHREADS) {
        int cout = g / (CIN * 27);
        int rem  = g % (CIN * 27);
        int cin  = rem / 27;
        int k    = rem % 27;
        int kdh  = k / 3;
        int kw   = k % 3;
        s_w[(cin * 9 + kdh) * 48 + kw * 16 + cout] = Wg[g];
    }
    if (tid < COUTC) s_bias[tid] = Bias[tid];

    // ---- Precompute tile-slot source offsets (cin-invariant) ----
    // slot s = tid + k*128: row r = s/80, pos p = s%80, window w = p/10,
    // in-window o = p%10 -> logical x lx = 8w + o (0..65), gx = lx-1.
    int soff[SLOTS_PER_THREAD];
#pragma unroll
    for (int k = 0; k < SLOTS_PER_THREAD; ++k) {
        int s = tid + k * NTHREADS;
        int off = -1;
        if (s < TILE_ELEMS) {
            int r  = s / IN_ROW;
            int p  = s % IN_ROW;
            int w  = p / WIN_W;
            int o  = p % WIN_W;
            int gx = 8 * w + o - 1;
            int gz = z  + r / IN_H - 1;
            int gy = y0 + r % IN_H - 1;
            if ((unsigned)gz < SDIM && (unsigned)gy < SDIM && (unsigned)gx < SDIM)
                off = (gz * SDIM + gy) * SDIM + gx;
            else {
                s_in[0][s] = 0.0f;
                s_in[1][s] = 0.0f;
            }
        }
        soff[k] = off;
    }
    __syncthreads();   // zeros + weights visible before compute / overwrite

    const float* Xb = X + (size_t)b * CIN * (SDIM * SDIM * SDIM);

    // ---- Prologue: async-load tile for cin=0 into buffer 0 ----
    {
        const float* Xc = Xb;
#pragma unroll
        for (int k = 0; k < SLOTS_PER_THREAD; ++k) {
            if (soff[k] >= 0) {
                uint32_t dst = smem_u32(&s_in[0][tid + k * NTHREADS]);
                asm volatile("cp.async.ca.shared.global [%0], [%1], 4;"
                             :: "r"(dst), "l"(Xc + soff[k]));
            }
        }
        asm volatile("cp.async.commit_group;");
    }

    unsigned long long accd[2][XPT];
#pragma unroll
    for (int cp = 0; cp < 2; ++cp)
#pragma unroll
        for (int j = 0; j < XPT; ++j) accd[cp][j] = 0ull;

#pragma unroll 1
    for (int cin = 0; cin < CIN; ++cin) {
        asm volatile("cp.async.wait_group 0;");
        __syncthreads();

        if (cin + 1 < CIN) {
            const float* Xc = Xb + (size_t)(cin + 1) * (SDIM * SDIM * SDIM);
            float* buf = s_in[(cin + 1) & 1];
#pragma unroll
            for (int k = 0; k < SLOTS_PER_THREAD; ++k) {
                if (soff[k] >= 0) {
                    uint32_t dst = smem_u32(&buf[tid + k * NTHREADS]);
                    asm volatile("cp.async.ca.shared.global [%0], [%1], 4;"
                                 :: "r"(dst), "l"(Xc + soff[k]));
                }
            }
            asm volatile("cp.async.commit_group;");
        }

        // ---- Compute: conflict-free window loads + FFMA2 over cout pairs ----
        const float* cur = s_in[cin & 1];
        const int wbase = cin * 9 * 48 + cg * CPT;
#pragma unroll
        for (int kd = 0; kd < 3; ++kd) {
#pragma unroll
            for (int kh = 0; kh < 3; ++kh) {
                const float* rowp = cur + (kd * IN_H + ty + kh) * IN_ROW + tx * WIN_W;
                const float2* r2 = reinterpret_cast<const float2*>(rowp);
                unsigned long long dup[WIN_W];
#pragma unroll
                for (int i = 0; i < 5; ++i) {
                    float2 p = r2[i];
                    PACKF2(dup[2 * i],     p.x, p.x);
                    PACKF2(dup[2 * i + 1], p.y, p.y);
                }

                // weights: one LDS.128 per kw -> (wA, wB) u64 halves, zero repack
                const float* wp = s_w + wbase + (kd * 3 + kh) * 48;
                unsigned long long wA[3], wB[3];
#pragma unroll
                for (int kw = 0; kw < 3; ++kw) {
                    ulonglong2 q = *reinterpret_cast<const ulonglong2*>(wp + kw * 16);
                    wA[kw] = q.x;
                    wB[kw] = q.y;
                }

#pragma unroll
                for (int kw = 0; kw < 3; ++kw) {
#pragma unroll
                    for (int j = 0; j < XPT; ++j) {
                        FMAF2(accd[0][j], dup[j + kw], wA[kw], accd[0][j]);
                        FMAF2(accd[1][j], dup[j + kw], wB[kw], accd[1][j]);
                    }
                }
            }
        }
    }

    // ---- Epilogue ----
    const int x0 = tx * XPT;
    const int y  = y0 + ty;
#pragma unroll
    for (int cp = 0; cp < 2; ++cp) {
        float o0[XPT], o1[XPT];
#pragma unroll
        for (int j = 0; j < XPT; ++j) UNPACKF2(o0[j], o1[j], accd[cp][j]);

        const int c0 = cg * CPT + 2 * cp;
        const float b0 = s_bias[c0];
        const float b1 = s_bias[c0 + 1];

        float* op0 = Out + ((((size_t)b * COUTC + c0)     * SDIM + z) * SDIM + y) * SDIM + x0;
        float* op1 = Out + ((((size_t)b * COUTC + c0 + 1) * SDIM + z) * SDIM + y) * SDIM + x0;

        reinterpret_cast<float4*>(op0)[0] = make_float4(o0[0] + b0, o0[1] + b0, o0[2] + b0, o0[3] + b0);
        reinterpret_cast<float4*>(op0)[1] = make_float4(o0[4] + b0, o0[5] + b0, o0[6] + b0, o0[7] + b0);
        reinterpret_cast<float4*>(op1)[0] = make_float4(o1[0] + b1, o1[1] + b1, o1[2] + b1, o1[3] + b1);
        reinterpret_cast<float4*>(op1)[1] = make_float4(o1[4] + b1, o1[5] + b1, o1[6] + b1, o1[7] + b1);
    }
}

extern "C" void kernel_launch(void* const* d_in, const int* in_sizes, int n_in,
                              void* d_out, int out_size)
{
    const float* x    = (const float*)d_in[0];
    const float* w    = (const float*)d_in[1];
    const float* bias = (const float*)d_in[2];
    float* out        = (float*)d_out;

    dim3 grid(SDIM, SDIM / TY, BATCH);
    conv3d_kernel<<<grid, NTHREADS>>>(x, w, bias, out);
}